// round 17
// baseline (speedup 1.0000x reference)
#include <cuda_runtime.h>
#include <cuda_bf16.h>
#include <cstdint>

#define Bb 32
#define Nn 1024
#define Ff 3
#define Tt 32
#define Kk 3
#define Cc 64
#define Ct 64
#define FT (Ff*Tt)   // 96

// Scratch
__device__ float gY[(size_t)Bb * Kk * Nn * FT];            // 37.7 MB
__device__ __nv_bfloat16 gAh[(size_t)Kk * Nn * Nn];
__device__ __nv_bfloat16 gAl[(size_t)Kk * Nn * Nn];
__device__ __nv_bfloat16 gXh[(size_t)Bb * FT * Nn];
__device__ __nv_bfloat16 gXl[(size_t)Bb * FT * Nn];
__device__ __align__(16) __nv_bfloat16 gWtH[3 * 64 * 72];
__device__ __align__(16) __nv_bfloat16 gWtL[3 * 64 * 72];

__device__ __forceinline__ uint32_t s2u(const void* p) {
    uint32_t a;
    asm("{ .reg .u64 t; cvta.to.shared.u64 t, %1; cvt.u32.u64 %0, t; }" : "=r"(a) : "l"(p));
    return a;
}
#define SWZ(o) ((o) ^ (((o) >> 3) & 0x70))

__device__ __forceinline__ void cp16(uint32_t dst, const void* src) {
    asm volatile("cp.async.cg.shared.global [%0], [%1], 16;" :: "r"(dst), "l"(src));
}
__device__ __forceinline__ void ldmx4(uint32_t* r, uint32_t addr) {
    asm volatile("ldmatrix.sync.aligned.m8n8.x4.shared.b16 {%0,%1,%2,%3}, [%4];"
                 : "=r"(r[0]), "=r"(r[1]), "=r"(r[2]), "=r"(r[3]) : "r"(addr));
}
__device__ __forceinline__ void mma16816(float* d, const uint32_t* a,
                                         uint32_t b0, uint32_t b1) {
    asm volatile(
        "mma.sync.aligned.m16n8k16.row.col.f32.bf16.bf16.f32 "
        "{%0,%1,%2,%3}, {%4,%5,%6,%7}, {%8,%9}, {%0,%1,%2,%3};"
        : "+f"(d[0]), "+f"(d[1]), "+f"(d[2]), "+f"(d[3])
        : "r"(a[0]), "r"(a[1]), "r"(a[2]), "r"(a[3]), "r"(b0), "r"(b1));
}

// ---------------------------------------------------------------------------
// Merged prep kernel (unchanged)
// ---------------------------------------------------------------------------
__global__ __launch_bounds__(256) void prep_all(
    const float* __restrict__ cheb, const float* __restrict__ x,
    const float* __restrict__ w_time)
{
    __shared__ float t[32][33];
    const int bid = blockIdx.x;
    const int tid = threadIdx.x;
    const int tx = tid & 31, ty = tid >> 5;

    if (bid < 3072) {
        const int k = bid >> 10, r = bid & 1023;
        const int m0 = (r >> 5) * 32, n0 = (r & 31) * 32;
        #pragma unroll
        for (int j = 0; j < 4; ++j)
            t[ty + j * 8][tx] = cheb[((size_t)(k * Nn + m0 + ty + j * 8)) * Nn + n0 + tx];
        __syncthreads();
        #pragma unroll
        for (int j = 0; j < 4; ++j) {
            const int n = n0 + ty + j * 8, m = m0 + tx;
            float v = t[tx][ty + j * 8];
            __nv_bfloat16 h = __float2bfloat16(v);
            __nv_bfloat16 l = __float2bfloat16(v - __bfloat162float(h));
            gAh[((size_t)(k * Nn + n)) * Nn + m] = h;
            gAl[((size_t)(k * Nn + n)) * Nn + m] = l;
        }
    } else if (bid < 6144) {
        const int r = bid - 3072;
        const int b = r / 96, r2 = r - b * 96;
        const int m0 = (r2 / 3) * 32, f0 = (r2 % 3) * 32;
        #pragma unroll
        for (int j = 0; j < 4; ++j)
            t[ty + j * 8][tx] = x[((size_t)(b * Nn + m0 + ty + j * 8)) * FT + f0 + tx];
        __syncthreads();
        #pragma unroll
        for (int j = 0; j < 4; ++j) {
            const int ft = f0 + ty + j * 8, m = m0 + tx;
            float v = t[tx][ty + j * 8];
            __nv_bfloat16 h = __float2bfloat16(v);
            __nv_bfloat16 l = __float2bfloat16(v - __bfloat162float(h));
            gXh[((size_t)b * FT + ft) * Nn + m] = h;
            gXl[((size_t)b * FT + ft) * Nn + m] = l;
        }
    } else {
        const int i = (bid - 6144) * 256 + tid;   // 3*64*72 = 13824
        if (i < 3 * 64 * 72) {
            int tap = i / (64 * 72), r = i - tap * (64 * 72);
            int c = r / 72, ci = r - c * 72;
            float v = (ci < 64) ? w_time[(c * 64 + ci) * 3 + tap] : 0.f;
            __nv_bfloat16 h = __float2bfloat16(v);
            __nv_bfloat16 l = __float2bfloat16(v - __bfloat162float(h));
            gWtH[i] = h;
            gWtL[i] = l;
        }
    }
}

// ---------------------------------------------------------------------------
// mma.sync bf16-split GEMM (round-14/16 version, measured 186us)
// ---------------------------------------------------------------------------
#define KC 64
#define ASZ (64 * KC * 2)
#define XSZ (96 * KC * 2)
#define SM_AH 0
#define SM_AL (SM_AH + ASZ)
#define SM_XH (SM_AL + ASZ)
#define SM_XL (SM_XH + XSZ)
#define GEMM_SMEM (SM_XL + XSZ)       // 40960

__global__ __launch_bounds__(128) void gemm_mma_kernel()
{
    extern __shared__ char smem[];
    const int n0 = blockIdx.x * 64;
    const int k  = blockIdx.y;
    const int b  = blockIdx.z;
    const int tid  = threadIdx.x;
    const int wid  = tid >> 5, lane = tid & 31;
    const int wm   = wid & 1;
    const int wn   = wid >> 1;
    const uint32_t smb = s2u(smem);

    const size_t aBase = ((size_t)k * Nn + n0) * Nn;
    const size_t xBase = (size_t)b * FT * Nn;

    float acc[2][6][4];
    #pragma unroll
    for (int i = 0; i < 2; ++i)
        #pragma unroll
        for (int j = 0; j < 6; ++j)
            #pragma unroll
            for (int q = 0; q < 4; ++q) acc[i][j][q] = 0.f;

    const int lrow = (lane & 7) + ((lane >> 3) & 1) * 8;
    const int lkb  = (lane >> 4) * 16;

    const int NCH = Nn / KC;   // 16
    for (int c = 0; c < NCH; ++c) {
        const size_t mOff = (size_t)c * KC;
        for (int i = tid; i < 512; i += 128) {
            const int row = i >> 3, seg = i & 7;
            const uint32_t so = SWZ(row * 128 + seg * 16);
            const size_t gi = aBase + (size_t)row * Nn + mOff + seg * 8;
            cp16(smb + SM_AH + so, gAh + gi);
            cp16(smb + SM_AL + so, gAl + gi);
        }
        for (int i = tid; i < 768; i += 128) {
            const int row = i >> 3, seg = i & 7;
            const uint32_t so = SWZ(row * 128 + seg * 16);
            const size_t gi = xBase + (size_t)row * Nn + mOff + seg * 8;
            cp16(smb + SM_XH + so, gXh + gi);
            cp16(smb + SM_XL + so, gXl + gi);
        }
        asm volatile("cp.async.commit_group;" ::: "memory");
        asm volatile("cp.async.wait_group 0;" ::: "memory");
        __syncthreads();

        #pragma unroll
        for (int ks = 0; ks < 4; ++ks) {
            const int kb = ks * 32 + lkb;
            uint32_t ah[2][4], al[2][4];
            #pragma unroll
            for (int mf = 0; mf < 2; ++mf) {
                const int r = wm * 32 + mf * 16 + lrow;
                const uint32_t off = SWZ(r * 128 + kb);
                ldmx4(ah[mf], smb + SM_AH + off);
                ldmx4(al[mf], smb + SM_AL + off);
            }
            uint32_t xh[3][4], xl[3][4];
            #pragma unroll
            for (int blk = 0; blk < 3; ++blk) {
                const int r = wn * 48 + blk * 16 + lrow;
                const uint32_t off = SWZ(r * 128 + kb);
                ldmx4(xh[blk], smb + SM_XH + off);
                ldmx4(xl[blk], smb + SM_XL + off);
            }
            #pragma unroll
            for (int mf = 0; mf < 2; ++mf)
                #pragma unroll
                for (int blk = 0; blk < 3; ++blk)
                    #pragma unroll
                    for (int sub = 0; sub < 2; ++sub) {
                        float* d = acc[mf][blk * 2 + sub];
                        mma16816(d, ah[mf], xh[blk][sub], xh[blk][sub + 2]);
                        mma16816(d, ah[mf], xl[blk][sub], xl[blk][sub + 2]);
                        mma16816(d, al[mf], xh[blk][sub], xh[blk][sub + 2]);
                    }
        }
        __syncthreads();
    }

    const int qrow = lane >> 2;
    const int qcol = (lane & 3) * 2;
    #pragma unroll
    for (int mf = 0; mf < 2; ++mf) {
        #pragma unroll
        for (int nf = 0; nf < 6; ++nf) {
            const int nrow = n0 + wm * 32 + mf * 16 + qrow;
            const int col  = wn * 48 + nf * 8 + qcol;
            float* base = gY + ((size_t)((b * Kk + k) * Nn) + nrow) * FT + col;
            *(float2*)(base)          = make_float2(acc[mf][nf][0], acc[mf][nf][1]);
            *(float2*)(base + 8 * FT) = make_float2(acc[mf][nf][2], acc[mf][nf][3]);
        }
    }
}

// ---------------------------------------------------------------------------
// Fused epilogue: GRP=16, tap-shifted conv, fused residual.
// NEW: theta stage thread=channel with 9 register coefs + broadcast float4 Y
// loads; boundary zeros folded in; residual/LN constants hoisted; 5 syncs/iter.
// ---------------------------------------------------------------------------
#define RW    144
#define EW    0
#define EWL   27648
#define ES    55296
#define ESL   74880
#define EPO   55296
#define EXS   94464
#define EYK   97536
#define EWR   106752            // [f][c] 192 f32
#define EBI   107520
#define EGM   107776
#define EBB   108032
#define EMU   108288
#define ERS   108800
#define ESMEM 109312
#define GRP   16
#define NITER (GRP / 4)
#define POW   130

__global__ __launch_bounds__(256) void fused_epi_tc(
    const float* __restrict__ x,
    const float* __restrict__ theta,
    const float* __restrict__ w_res,
    const float* __restrict__ b_time, const float* __restrict__ b_res,
    const float* __restrict__ gamma,  const float* __restrict__ beta,
    float* __restrict__ out)
{
    extern __shared__ char smem[];
    float* smf = (float*)smem;
    const uint32_t smb = s2u(smem);
    const int ng0 = blockIdx.x * GRP;
    const int b   = blockIdx.y;
    const int tid = threadIdx.x;
    const int wid = tid >> 5, lane = tid & 31;
    const int wm  = wid & 1, wn = wid >> 1;
    const int lrow = (lane & 7) + ((lane >> 3) & 1) * 8;
    const int lkb  = (lane >> 4) * 16;
    const int qrow = lane >> 2, qcol = (lane & 3) * 2;

    // theta stage mapping: thread = (nqT, channel cA)
    const int nqT = tid >> 6;
    const int cA  = tid & 63;
    // LN / normalize mappings
    const int cpr  = (tid & 63) >> 1;
    const int tHv  = (tid & 1) * 16;
    const int colS = tid >> 1;
    const int sS   = tid & 1;

    // ---- persistent: W taps via cp.async, scalars ----
    for (int i = tid; i < 1728; i += 256) {
        cp16(smb + EW  + i * 16, (const char*)gWtH + i * 16);
        cp16(smb + EWL + i * 16, (const char*)gWtL + i * 16);
    }
    asm volatile("cp.async.commit_group;" ::: "memory");
    if (tid < 192) { int c = tid / 3, f = tid - c * 3; smf[EWR/4 + f * 64 + c] = w_res[tid]; }
    if (tid < 64) {
        smf[EBI/4 + tid] = b_time[tid] + b_res[tid];
        smf[EGM/4 + tid] = gamma[tid];
        smf[EBB/4 + tid] = beta[tid];
    }
    // theta coefs: 9 per thread, straight from gmem (coalesced)
    float th[9];
    #pragma unroll
    for (int kf = 0; kf < 9; ++kf) th[kf] = theta[kf * 64 + cA];
    asm volatile("cp.async.wait_group 0;" ::: "memory");
    __syncthreads();

    // hoist iter-invariant constants
    float rw0[4], rw1[4], rw2[4], rbi[4];   // [mf*2+rr] for channels of fused stage
    #pragma unroll
    for (int mf = 0; mf < 2; ++mf)
        #pragma unroll
        for (int rr = 0; rr < 2; ++rr) {
            const int c = wm * 32 + mf * 16 + qrow + rr * 8;
            rw0[mf * 2 + rr] = smf[EWR/4 + 0 * 64 + c];
            rw1[mf * 2 + rr] = smf[EWR/4 + 1 * 64 + c];
            rw2[mf * 2 + rr] = smf[EWR/4 + 2 * 64 + c];
            rbi[mf * 2 + rr] = smf[EBI/4 + c];
        }
    const int cloN = 2 * cpr, chiN = cloN + 1;
    const float gloN = smf[EGM/4 + cloN], blN = smf[EBB/4 + cloN];
    const float ghiN = smf[EGM/4 + chiN], bhN = smf[EBB/4 + chiN];

    auto issue_prefetch = [&](int npx, int buf) {
        const int n0x = ng0 + 4 * npx;
        for (int i = tid; i < 384; i += 256) {
            if (i < 288) {
                const int h = i / 72, r = i - h * 72;
                const int k = r / 24, seg = r - k * 24;
                const uint32_t dst = smb + EYK + buf * 4608 + ((h * 3 + k) * 96 + seg * 4) * 4;
                cp16(dst, gY + ((size_t)((b * Kk + k) * Nn + n0x + h)) * FT + seg * 4);
            } else {
                const int j = i - 288;
                const int h = j / 24, seg = j - h * 24;
                const uint32_t dst = smb + EXS + buf * 1536 + (h * 96 + seg * 4) * 4;
                cp16(dst, x + ((size_t)(b * Nn + n0x + h)) * FT + seg * 4);
            }
        }
        asm volatile("cp.async.commit_group;" ::: "memory");
    };

    issue_prefetch(0, 0);

    #pragma unroll 1
    for (int np = 0; np < NITER; ++np) {
        const int buf = np & 1;
        const int n0 = ng0 + 4 * np;

        if (np + 1 < NITER) {
            issue_prefetch(np + 1, buf ^ 1);
            asm volatile("cp.async.wait_group 1;" ::: "memory");
        } else {
            asm volatile("cp.async.wait_group 0;" ::: "memory");
        }
        __syncthreads();   // prefetched Y/x visible; prior iter's po reads done

        // ---- theta (register coefs, broadcast Y) + relu + split -> S column ----
        {
            float sacc[32];
            #pragma unroll
            for (int j = 0; j < 32; ++j) sacc[j] = 0.f;
            const float* yb = &smf[EYK/4 + buf * 1152 + nqT * 3 * 96];
            #pragma unroll
            for (int kf = 0; kf < 9; ++kf) {
                const int k = kf / 3, f = kf - k * 3;
                const float4* yp = (const float4*)(yb + k * 96 + f * 32);
                const float coef = th[kf];
                #pragma unroll
                for (int j = 0; j < 8; ++j) {
                    const float4 yv = yp[j];
                    sacc[4 * j + 0] += coef * yv.x;
                    sacc[4 * j + 1] += coef * yv.y;
                    sacc[4 * j + 2] += coef * yv.z;
                    sacc[4 * j + 3] += coef * yv.w;
                }
            }
            char* sh = smem + ES  + (nqT * 34 + 1) * RW + cA * 2;
            char* sl = smem + ESL + (nqT * 34 + 1) * RW + cA * 2;
            #pragma unroll
            for (int t = 0; t < 32; ++t) {
                const float v = fmaxf(sacc[t], 0.f);
                const __nv_bfloat16 h = __float2bfloat16(v);
                const __nv_bfloat16 l = __float2bfloat16(v - __bfloat162float(h));
                *(__nv_bfloat16*)(sh + t * RW) = h;
                *(__nv_bfloat16*)(sl + t * RW) = l;
            }
            // boundary zeros (rows 0 and 33 of this nq)
            *(__nv_bfloat16*)(sh - RW)      = __float2bfloat16(0.f);
            *(__nv_bfloat16*)(sl - RW)      = __float2bfloat16(0.f);
            *(__nv_bfloat16*)(sh + 32 * RW) = __float2bfloat16(0.f);
            *(__nv_bfloat16*)(sl + 32 * RW) = __float2bfloat16(0.f);
        }
        __syncthreads();

        // ---- conv GEMM ----
        float acc[2][4][4];
        #pragma unroll
        for (int i = 0; i < 2; ++i)
            #pragma unroll
            for (int j = 0; j < 4; ++j)
                #pragma unroll
                for (int q = 0; q < 4; ++q) acc[i][j][q] = 0.f;

        #pragma unroll
        for (int tap = 0; tap < 3; ++tap) {
            #pragma unroll
            for (int ks = 0; ks < 4; ++ks) {
                const int kb = ks * 32 + lkb;
                uint32_t ah[2][4], al[2][4], bh[2][4], bl[2][4];
                #pragma unroll
                for (int mf = 0; mf < 2; ++mf) {
                    const uint32_t aoff = (tap * 64 + wm * 32 + mf * 16 + lrow) * RW + kb;
                    ldmx4(ah[mf], smb + EW  + aoff);
                    ldmx4(al[mf], smb + EWL + aoff);
                }
                #pragma unroll
                for (int cb = 0; cb < 2; ++cb) {
                    const uint32_t boff = (wn * 34 + cb * 16 + lrow + tap) * RW + kb;
                    ldmx4(bh[cb], smb + ES  + boff);
                    ldmx4(bl[cb], smb + ESL + boff);
                }
                #pragma unroll
                for (int mf = 0; mf < 2; ++mf)
                    #pragma unroll
                    for (int cb = 0; cb < 2; ++cb)
                        #pragma unroll
                        for (int sub = 0; sub < 2; ++sub) {
                            float* d = acc[mf][cb * 2 + sub];
                            mma16816(d, ah[mf], bh[cb][sub], bh[cb][sub + 2]);
                            mma16816(d, ah[mf], bl[cb][sub], bl[cb][sub + 2]);
                            mma16816(d, al[mf], bh[cb][sub], bh[cb][sub + 2]);
                        }
            }
        }
        __syncthreads();   // all S reads done -> safe to overlay po

        // ---- fused: bias + residual + relu in registers, write po ----
        {
            float* po = smf + EPO/4;
            const float* xs = &smf[EXS/4 + buf * 384 + wn * 96];
            #pragma unroll
            for (int mf = 0; mf < 2; ++mf) {
                #pragma unroll
                for (int rr = 0; rr < 2; ++rr) {
                    const int c = wm * 32 + mf * 16 + qrow + rr * 8;
                    const float w0 = rw0[mf * 2 + rr], w1 = rw1[mf * 2 + rr];
                    const float w2 = rw2[mf * 2 + rr], bi = rbi[mf * 2 + rr];
                    #pragma unroll
                    for (int nf = 0; nf < 4; ++nf) {
                        const int t0 = nf * 8 + qcol;
                        float v0 = acc[mf][nf][rr * 2 + 0] + bi
                                 + w0 * xs[t0] + w1 * xs[32 + t0] + w2 * xs[64 + t0];
                        float v1 = acc[mf][nf][rr * 2 + 1] + bi
                                 + w0 * xs[t0 + 1] + w1 * xs[32 + t0 + 1] + w2 * xs[64 + t0 + 1];
                        *(float2*)&po[c * POW + wn * 32 + t0] =
                            make_float2(fmaxf(v0, 0.f), fmaxf(v1, 0.f));
                    }
                }
            }
        }
        __syncthreads();

        // ---- LN stats ----
        {
            const float* po = smf + EPO/4;
            float sum = 0.f, sq = 0.f;
            #pragma unroll
            for (int q = 0; q < 32; ++q) {
                const float v = po[(sS * 32 + q) * POW + colS];
                sum += v; sq += v * v;
            }
            sum += __shfl_xor_sync(0xffffffffu, sum, 1);
            sq  += __shfl_xor_sync(0xffffffffu, sq,  1);
            if (sS == 0) {
                const float m = sum * (1.f / Ct);
                const float var = sq * (1.f / Ct) - m * m;
                smf[EMU/4 + colS] = m;
                smf[ERS/4 + colS] = rsqrtf(var + 1e-5f);
            }
        }
        __syncthreads();

        // ---- normalize (read po) + store ----
        {
            const float* po = smf + EPO/4;
            float olo[16], ohi[16];
            #pragma unroll
            for (int j = 0; j < 16; ++j) {
                const int col = nqT * 32 + tHv + j;
                const float mu = smf[EMU/4 + col];
                const float rs = smf[ERS/4 + col];
                olo[j] = (po[cloN * POW + col] - mu) * rs * gloN + blN;
                ohi[j] = (po[chiN * POW + col] - mu) * rs * ghiN + bhN;
            }
            float* obase = out + ((size_t)(b * Nn + n0 + nqT)) * Ct * Tt;
            #pragma unroll
            for (int q = 0; q < 4; ++q) {
                *(float4*)(obase + cloN * Tt + tHv + q * 4) =
                    make_float4(olo[q*4], olo[q*4+1], olo[q*4+2], olo[q*4+3]);
                *(float4*)(obase + chiN * Tt + tHv + q * 4) =
                    make_float4(ohi[q*4], ohi[q*4+1], ohi[q*4+2], ohi[q*4+3]);
            }
        }
        // loop-top sync protects po (overlaying S) before next theta writes
    }
}

// ---------------------------------------------------------------------------
extern "C" void kernel_launch(void* const* d_in, const int* in_sizes, int n_in,
                              void* d_out, int out_size)
{
    const float* x      = (const float*)d_in[0];
    const float* cheb   = (const float*)d_in[1];
    const float* theta  = (const float*)d_in[2];
    const float* w_time = (const float*)d_in[3];
    const float* b_time = (const float*)d_in[4];
    const float* w_res  = (const float*)d_in[5];
    const float* b_res  = (const float*)d_in[6];
    const float* gamma  = (const float*)d_in[7];
    const float* beta   = (const float*)d_in[8];
    float* out = (float*)d_out;

    cudaFuncSetAttribute(gemm_mma_kernel,
                         cudaFuncAttributeMaxDynamicSharedMemorySize, GEMM_SMEM);
    cudaFuncSetAttribute(fused_epi_tc,
                         cudaFuncAttributeMaxDynamicSharedMemorySize, ESMEM);

    prep_all<<<6198, 256>>>(cheb, x, w_time);
    gemm_mma_kernel<<<dim3(16, 3, 32), 128, GEMM_SMEM>>>();
    fused_epi_tc<<<dim3(Nn / GRP, Bb), 256, ESMEM>>>(
        x, theta, w_res, b_time, b_res, gamma, beta, out);
}